// round 12
// baseline (speedup 1.0000x reference)
#include <cuda_runtime.h>
#include <cuda_bf16.h>
#include <mma.h>
#include <math.h>

using namespace nvcuda;

#define B_TOT 16384
#define S_DIM 300
#define A_DIM 30
#define M_PROTO 16
#define NT 256
#define ROWS 16
#define NBLK (B_TOT / ROWS)
#define DH 260

// fp32 intermediates (precompute1)
__device__ float G_g[256 * 128];    // G[k][mn], scale folded
__device__ float c_g[128];
__device__ float conc_g[M_PROTO * A_DIM];
// bf16 hi/lo split tables (precompute2)
__device__ __align__(16) __nv_bfloat16 W1hi_g[304 * 256];
__device__ __align__(16) __nv_bfloat16 W1lo_g[304 * 256];
__device__ __align__(16) __nv_bfloat16 Ghi_g[256 * 128];
__device__ __align__(16) __nv_bfloat16 Glo_g[256 * 128];

// ---------------------------------------------------------------------------
// Precompute1: blocks 0..255 -> G row k; 256 -> c_g; 257..272 -> conc_g[m]
// ---------------------------------------------------------------------------
__global__ void __launch_bounds__(256) precompute_kernel(
    const float* __restrict__ pk, const float* __restrict__ enc_W2,
    const float* __restrict__ enc_b2, const float* __restrict__ dW1,
    const float* __restrict__ db1, const float* __restrict__ dW2,
    const float* __restrict__ db2) {
    const int bk = blockIdx.x;
    const int t = threadIdx.x;
    if (bk < 256) {
        __shared__ float w2row[2048];
        __shared__ float pks[16 * 257];
        __shared__ float part[256];
        for (int i = t; i < 2048; i += 256) w2row[i] = enc_W2[bk * 2048 + i];
        for (int i = t; i < 4096; i += 256)
            pks[(i >> 8) * 257 + (i & 255)] = pk[i];
        __syncthreads();
        const int mn = t & 127, half = t >> 7;
        const int m = mn >> 4, n = mn & 15;
        const float* wr = w2row + m * 256 + half * 128;
        const float* pr = pks + n * 257 + half * 128;
        float s = 0.f;
        #pragma unroll 8
        for (int e = 0; e < 128; e++) s += wr[e] * pr[e];
        part[t] = s;
        __syncthreads();
        if (t < 128) G_g[bk * 128 + t] = (part[t] + part[t + 128]) * 0.0625f;
    } else if (bk == 256) {
        __shared__ float part[256];
        const int mn = t & 127, half = t >> 7;
        const int m = mn >> 4, n = mn & 15;
        const float4* br = (const float4*)(enc_b2 + m * 256 + half * 128);
        const float4* pr = (const float4*)(pk + n * 256 + half * 128);
        float s = 0.f;
        #pragma unroll 8
        for (int e = 0; e < 32; e++) {
            const float4 b4 = __ldg(&br[e]);
            const float4 p4 = __ldg(&pr[e]);
            s += b4.x * p4.x + b4.y * p4.y + b4.z * p4.z + b4.w * p4.w;
        }
        part[t] = s;
        __syncthreads();
        if (t < 128) c_g[t] = (part[t] + part[t + 128]) * 0.0625f;
    } else {
        const int m = bk - 257;
        __shared__ float part[256];
        __shared__ float hd[128];
        const int h = t & 127, eh = t >> 7;
        const float* pkm = pk + m * 256 + eh * 128;
        const float* wcol = dW1 + (m * 256 + eh * 128) * 128 + h;
        float s = 0.f;
        #pragma unroll 8
        for (int e = 0; e < 128; e++) s += pkm[e] * wcol[e * 128];
        part[t] = s;
        __syncthreads();
        if (t < 128)
            hd[t] = fmaxf(part[t] + part[t + 128] + db1[m * 128 + t], 0.f);
        __syncthreads();
        if (t < A_DIM) {
            float s2 = db2[m * A_DIM + t];
            const float* w2 = dW2 + m * 128 * A_DIM + t;
            #pragma unroll 8
            for (int h2 = 0; h2 < 128; h2++)
                s2 += hd[h2] * __ldg(w2 + h2 * A_DIM);
            conc_g[m * A_DIM + t] = fmaxf(s2, 0.f) + log1pf(expf(-fabsf(s2)));
        }
    }
}

// ---------------------------------------------------------------------------
// Precompute2: bf16 hi/lo split of W1 (zero-padded K 300->304) and G
// ---------------------------------------------------------------------------
__global__ void __launch_bounds__(256) convert_kernel(const float* __restrict__ W1) {
    const int idx = blockIdx.x * 256 + threadIdx.x;
    if (idx < 304 * 256) {
        const int k = idx >> 8, n = idx & 255;
        const float w = (k < 300) ? W1[k * 256 + n] : 0.f;
        const __nv_bfloat16 hi = __float2bfloat16(w);
        W1hi_g[idx] = hi;
        W1lo_g[idx] = __float2bfloat16(w - __bfloat162float(hi));
    } else {
        const int j = idx - 304 * 256;
        if (j < 256 * 128) {
            const float g = G_g[j];
            const __nv_bfloat16 hi = __float2bfloat16(g);
            Ghi_g[j] = hi;
            Glo_g[j] = __float2bfloat16(g - __bfloat162float(hi));
        }
    }
}

// ---------------------------------------------------------------------------
// Main kernel: 1024 blocks x 256 threads (8 warps), 16 batch rows/block.
// GEMMs via wmma bf16 hi/lo split (3 mma per tile), fp32 accumulate.
// ---------------------------------------------------------------------------
__global__ void __launch_bounds__(NT, 2) main_kernel(
    const float* __restrict__ state, const float* __restrict__ fitness,
    const float* __restrict__ pk, const float* __restrict__ b1,
    const float* __restrict__ ln_g, const float* __restrict__ ln_b,
    const float* __restrict__ tc_W, const float* __restrict__ tc_b,
    const float* __restrict__ tc_cW, const float* __restrict__ tc_cb,
    const float* __restrict__ w_prev, float* __restrict__ out) {
    extern __shared__ char smraw[];
    float* st            = (float*)smraw;                         // 4800 f
    float* dh            = (float*)(smraw + 19200);               // 16x260 f
    __nv_bfloat16* Ahi   = (__nv_bfloat16*)(smraw + 35840);       // 16x304
    __nv_bfloat16* Alo   = (__nv_bfloat16*)(smraw + 45568);       // 16x304
    __nv_bfloat16* Bhi   = (__nv_bfloat16*)(smraw + 55296);       // 2 x 4096
    __nv_bfloat16* Blo   = (__nv_bfloat16*)(smraw + 71680);       // 2 x 4096
    float* dds           = (float*)(smraw + 88064);               // 256 f
    float* concs         = (float*)(smraw + 89088);               // 480 f
    float* stats         = (float*)(smraw + 91008);               // 48 f
    float* lgt           = st;                                    // alias (st dead)
    __nv_bfloat16* hhi   = Ahi;                                   // alias (A dead)
    __nv_bfloat16* hlo   = Alo;

    const int tid = threadIdx.x;
    const int lane = tid & 31;
    const int wid = tid >> 5;
    const int b0 = blockIdx.x * ROWS;
    const unsigned FULL = 0xffffffffu;

    // ---- cooperative loads ----
    {
        const float4* gsrc = (const float4*)(state + (size_t)b0 * S_DIM);
        float4* sdst = (float4*)st;
        for (int i = tid; i < 1200; i += NT) sdst[i] = gsrc[i];
        for (int i = tid; i < M_PROTO * A_DIM; i += NT) concs[i] = conc_g[i];
    }
    __syncthreads();

    // ---- A = st split into bf16 hi/lo, K padded to 304 ----
    for (int i = tid; i < 16 * 304; i += NT) {
        const int r = i / 304, k = i - r * 304;
        const float v = (k < 300) ? st[r * 300 + k] : 0.f;
        const __nv_bfloat16 hi = __float2bfloat16(v);
        Ahi[i] = hi;
        Alo[i] = __float2bfloat16(v - __bfloat162float(hi));
    }

    // ---- stage 1: market features + danger + crisis (warp: 2 rows) ----
    {
        const int rA = wid, rB = wid + 8;
        const float* sA = st + rA * S_DIM;
        const float* sB = st + rB * S_DIM;
        float mfa[12], mfb[12];
        #pragma unroll
        for (int pass = 0; pass < 2; pass++) {
            const float* srow = pass ? sB : sA;
            float* mf = pass ? mfb : mfa;
            float p = 0.f, sh = 0.f;
            if (lane < 30) { p = srow[1 + lane]; sh = srow[31 + lane]; }
            float sp = p, spp = p * p, sps = p * sh;
            #pragma unroll
            for (int m2 = 16; m2 >= 1; m2 >>= 1) {
                sp  += __shfl_xor_sync(FULL, sp, m2);
                spp += __shfl_xor_sync(FULL, spp, m2);
                sps += __shfl_xor_sync(FULL, sps, m2);
            }
            const float bal = srow[0];
            const float mean = sp * (1.f / 30.f);
            const float var = fmaxf((spp - 30.f * mean * mean) * (1.f / 29.f), 0.f);
            mf[0] = bal; mf[1] = mean;
            mf[2] = sqrtf(var) + 1e-8f;
            mf[3] = bal / (bal + sps + 1e-8f);
            #pragma unroll
            for (int i = 0; i < 8; i++) mf[4 + i] = srow[61 + 30 * i];
        }
        float cpA = 0.f, cpB = 0.f;
        #pragma unroll
        for (int i = 0; i < 8; i++) {
            const int j = lane + 32 * i;
            const float bj = tc_b[j];
            float aA = bj, aB = bj;
            #pragma unroll
            for (int f = 0; f < 12; f++) {
                const float w = tc_W[f * 256 + j];
                aA += mfa[f] * w; aB += mfb[f] * w;
            }
            const float dA = tanhf(aA), dB = tanhf(aB);
            dh[rA * DH + j] = dA;
            dh[rB * DH + j] = dB;
            const float cw = tc_cW[j];
            cpA += dA * cw; cpB += dB * cw;
        }
        #pragma unroll
        for (int m2 = 16; m2 >= 1; m2 >>= 1) {
            cpA += __shfl_xor_sync(FULL, cpA, m2);
            cpB += __shfl_xor_sync(FULL, cpB, m2);
        }
        if (lane == 0) {
            const float cb = tc_cb[0];
            stats[32 + rA] = 1.f / (1.f + expf(-(cpA + cb)));
            stats[32 + rB] = 1.f / (1.f + expf(-(cpB + cb)));
        }
    }
    __syncthreads();

    // ---- dd[r][n] = scale * danger[r].pk[n]  (fp32 exact) ----
    {
        const int n = tid >> 4, kq = tid & 15;
        float pkc[16];
        {
            const float4* pr = (const float4*)(pk + n * 256 + kq * 16);
            #pragma unroll
            for (int i = 0; i < 4; i++) {
                const float4 p4 = __ldg(&pr[i]);
                pkc[i * 4 + 0] = p4.x; pkc[i * 4 + 1] = p4.y;
                pkc[i * 4 + 2] = p4.z; pkc[i * 4 + 3] = p4.w;
            }
        }
        #pragma unroll 4
        for (int r = 0; r < ROWS; r++) {
            const float* dr = dh + r * DH + kq * 16;
            float s = 0.f;
            #pragma unroll
            for (int i = 0; i < 4; i++) {
                const float4 d4 = *(const float4*)&dr[i * 4];
                s += d4.x * pkc[i * 4] + d4.y * pkc[i * 4 + 1] +
                     d4.z * pkc[i * 4 + 2] + d4.w * pkc[i * 4 + 3];
            }
            #pragma unroll
            for (int m2 = 8; m2 >= 1; m2 >>= 1) s += __shfl_xor_sync(FULL, s, m2);
            if (kq == 0) dds[r * 16 + n] = s * 0.0625f;
        }
    }
    // prologue: stage W1 chunk 0 into buffer 0
    {
        const uint4* srch = (const uint4*)(W1hi_g);
        const uint4* srcl = (const uint4*)(W1lo_g);
        uint4* dsth = (uint4*)Bhi;
        uint4* dstl = (uint4*)Blo;
        dsth[tid] = srch[tid]; dsth[tid + 256] = srch[tid + 256];
        dstl[tid] = srcl[tid]; dstl[tid + 256] = srcl[tid + 256];
    }
    __syncthreads();   // danger consumed; staging visible

    // ---- W1 GEMM: h_raw[16x256] = A[16x304] @ W1[304x256], bf16 split ----
    {
        const int n0 = wid * 32;
        wmma::fragment<wmma::matrix_a, 16, 16, 16, __nv_bfloat16, wmma::row_major> fah, fal;
        wmma::fragment<wmma::matrix_b, 16, 16, 16, __nv_bfloat16, wmma::row_major> fbh0, fbl0, fbh1, fbl1;
        wmma::fragment<wmma::accumulator, 16, 16, 16, float> c0, c1;
        wmma::fill_fragment(c0, 0.f);
        wmma::fill_fragment(c1, 0.f);
        for (int kc = 0; kc < 19; kc++) {
            const int s = kc & 1;
            if (kc < 18) {
                const uint4* srch = (const uint4*)(W1hi_g + (kc + 1) * 4096);
                const uint4* srcl = (const uint4*)(W1lo_g + (kc + 1) * 4096);
                uint4* dsth = (uint4*)(Bhi + (s ^ 1) * 4096);
                uint4* dstl = (uint4*)(Blo + (s ^ 1) * 4096);
                dsth[tid] = srch[tid]; dsth[tid + 256] = srch[tid + 256];
                dstl[tid] = srcl[tid]; dstl[tid + 256] = srcl[tid + 256];
            }
            const __nv_bfloat16* bsh = Bhi + s * 4096;
            const __nv_bfloat16* bsl = Blo + s * 4096;
            wmma::load_matrix_sync(fah, Ahi + kc * 16, 304);
            wmma::load_matrix_sync(fal, Alo + kc * 16, 304);
            wmma::load_matrix_sync(fbh0, bsh + n0, 256);
            wmma::load_matrix_sync(fbl0, bsl + n0, 256);
            wmma::load_matrix_sync(fbh1, bsh + n0 + 16, 256);
            wmma::load_matrix_sync(fbl1, bsl + n0 + 16, 256);
            wmma::mma_sync(c0, fah, fbh0, c0);
            wmma::mma_sync(c0, fah, fbl0, c0);
            wmma::mma_sync(c0, fal, fbh0, c0);
            wmma::mma_sync(c1, fah, fbh1, c1);
            wmma::mma_sync(c1, fah, fbl1, c1);
            wmma::mma_sync(c1, fal, fbh1, c1);
            __syncthreads();
        }
        wmma::store_matrix_sync(dh + n0, c0, DH, wmma::mem_row_major);
        wmma::store_matrix_sync(dh + n0 + 16, c1, DH, wmma::mem_row_major);
    }
    __syncthreads();

    // ---- layernorm stats (bias b1 folded at read) ----
    for (int rr = 0; rr < 2; rr++) {
        const int r = wid + rr * 8;
        float s1 = 0.f, s2 = 0.f;
        #pragma unroll
        for (int i = 0; i < 8; i++) {
            const int j = lane + 32 * i;
            const float v = dh[r * DH + j] + b1[j];
            s1 += v; s2 += v * v;
        }
        #pragma unroll
        for (int m2 = 16; m2 >= 1; m2 >>= 1) {
            s1 += __shfl_xor_sync(FULL, s1, m2);
            s2 += __shfl_xor_sync(FULL, s2, m2);
        }
        if (lane == 0) {
            const float mu = s1 * (1.f / 256.f);
            const float var = s2 * (1.f / 256.f) - mu * mu;
            stats[r] = mu;
            stats[16 + r] = rsqrtf(fmaxf(var, 0.f) + 1e-5f);
        }
    }
    __syncthreads();
    // ---- normalize + relu -> bf16 hi/lo h; prologue-stage G chunk 0 ----
    {
        const float g = ln_g[tid], bb = ln_b[tid], bias = b1[tid];
        #pragma unroll
        for (int r = 0; r < ROWS; r++) {
            const float raw = dh[r * DH + tid] + bias;
            const float v = fmaxf((raw - stats[r]) * stats[16 + r] * g + bb, 0.f);
            const __nv_bfloat16 hi = __float2bfloat16(v);
            hhi[r * 256 + tid] = hi;
            hlo[r * 256 + tid] = __float2bfloat16(v - __bfloat162float(hi));
        }
        ((uint4*)Bhi)[tid] = ((const uint4*)Ghi_g)[tid];
        ((uint4*)Blo)[tid] = ((const uint4*)Glo_g)[tid];
    }
    __syncthreads();

    // ---- logits GEMM: lgt[16x128] = h[16x256] @ G[256x128], bf16 split ----
    {
        const int n0 = wid * 16;
        wmma::fragment<wmma::matrix_a, 16, 16, 16, __nv_bfloat16, wmma::row_major> fah, fal;
        wmma::fragment<wmma::matrix_b, 16, 16, 16, __nv_bfloat16, wmma::row_major> fbh, fbl;
        wmma::fragment<wmma::accumulator, 16, 16, 16, float> cl;
        wmma::fill_fragment(cl, 0.f);
        for (int kc = 0; kc < 16; kc++) {
            const int s = kc & 1;
            if (kc < 15) {
                ((uint4*)(Bhi + (s ^ 1) * 4096))[tid] =
                    ((const uint4*)(Ghi_g + (kc + 1) * 2048))[tid];
                ((uint4*)(Blo + (s ^ 1) * 4096))[tid] =
                    ((const uint4*)(Glo_g + (kc + 1) * 2048))[tid];
            }
            wmma::load_matrix_sync(fah, hhi + kc * 16, 256);
            wmma::load_matrix_sync(fal, hlo + kc * 16, 256);
            wmma::load_matrix_sync(fbh, Bhi + s * 4096 + n0, 128);
            wmma::load_matrix_sync(fbl, Blo + s * 4096 + n0, 128);
            wmma::mma_sync(cl, fah, fbh, cl);
            wmma::mma_sync(cl, fah, fbl, cl);
            wmma::mma_sync(cl, fal, fbh, cl);
            __syncthreads();
        }
        wmma::store_matrix_sync(lgt + n0, cl, 128, wmma::mem_row_major);
    }
    __syncthreads();

    // ---- softmax over protos, weight mixing, action softmax (warp/row) ----
    for (int rr = 0; rr < 2; rr++) {
        const int r = wid + rr * 8;
        const int n = lane & 15;
        const int mh = lane >> 4;
        float wot = 0.f;
        #pragma unroll
        for (int mm = 0; mm < 4; mm++) {
            const int m = mm * 2 + mh;
            const float v = lgt[r * 128 + m * 16 + n] + c_g[m * 16 + n] + dds[r * 16 + n];
            float mx = v;
            #pragma unroll
            for (int m2 = 8; m2 >= 1; m2 >>= 1) mx = fmaxf(mx, __shfl_xor_sync(FULL, mx, m2));
            const float e = expf(v - mx);
            float s = e;
            #pragma unroll
            for (int m2 = 8; m2 >= 1; m2 >>= 1) s += __shfl_xor_sync(FULL, s, m2);
            wot += e / s;
        }
        wot += __shfl_xor_sync(FULL, wot, 16);
        wot *= 0.125f;

        const float f = fitness[(b0 + r) * 16 + n];
        float wr = w_prev[n] * expf(0.1f * f);
        float swr = wr;
        #pragma unroll
        for (int m2 = 8; m2 >= 1; m2 >>= 1) swr += __shfl_xor_sync(FULL, swr, m2);
        wr /= (swr + 1e-8f);

        const float crisis = stats[32 + r];
        const float alpha = 0.06f + 0.24f * (1.f - crisis);
        float w = alpha * wot + (1.f - alpha) * wr;
        float sw = w;
        #pragma unroll
        for (int m2 = 8; m2 >= 1; m2 >>= 1) sw += __shfl_xor_sync(FULL, sw, m2);
        w /= (sw + 1e-8f);
        if (lane < 16) dds[r * 16 + n] = w;
        __syncwarp();

        float mix = __int_as_float(0xff800000);
        if (lane < 30) {
            mix = 1.f;
            #pragma unroll
            for (int m = 0; m < 16; m++) mix += dds[r * 16 + m] * concs[m * 30 + lane];
        }
        float mx = mix;
        #pragma unroll
        for (int m2 = 16; m2 >= 1; m2 >>= 1) mx = fmaxf(mx, __shfl_xor_sync(FULL, mx, m2));
        float e = (lane < 30) ? expf(mix - mx) : 0.f;
        float s = e;
        #pragma unroll
        for (int m2 = 16; m2 >= 1; m2 >>= 1) s += __shfl_xor_sync(FULL, s, m2);
        float p = e / s;
        float sp = p;
        #pragma unroll
        for (int m2 = 16; m2 >= 1; m2 >>= 1) sp += __shfl_xor_sync(FULL, sp, m2);
        p = p / (sp + 1e-8f);
        if (lane < 30) out[(b0 + r) * 30 + lane] = p;
    }
}

// ---------------------------------------------------------------------------
extern "C" void kernel_launch(void* const* d_in, const int* in_sizes, int n_in,
                              void* d_out, int out_size) {
    const float* state   = (const float*)d_in[0];
    const float* fitness = (const float*)d_in[1];
    const float* pk      = (const float*)d_in[2];
    const float* W1      = (const float*)d_in[3];
    const float* b1      = (const float*)d_in[4];
    const float* ln_g    = (const float*)d_in[5];
    const float* ln_b    = (const float*)d_in[6];
    const float* W2      = (const float*)d_in[7];
    const float* b2      = (const float*)d_in[8];
    const float* dW1     = (const float*)d_in[9];
    const float* db1     = (const float*)d_in[10];
    const float* dW2     = (const float*)d_in[11];
    const float* db2     = (const float*)d_in[12];
    const float* tcW     = (const float*)d_in[13];
    const float* tcb     = (const float*)d_in[14];
    const float* tccW    = (const float*)d_in[15];
    const float* tccb    = (const float*)d_in[16];
    const float* w_prev  = (const float*)d_in[19];
    float* out = (float*)d_out;

    precompute_kernel<<<273, 256>>>(pk, W2, b2, dW1, db1, dW2, db2);
    convert_kernel<<<432, 256>>>(W1);

    const int smem_bytes = 91200;
    cudaFuncSetAttribute(main_kernel, cudaFuncAttributeMaxDynamicSharedMemorySize,
                         smem_bytes);
    main_kernel<<<NBLK, NT, smem_bytes>>>(state, fitness, pk, b1, ln_g, ln_b,
                                          tcW, tcb, tccW, tccb, w_prev, out);
}

// round 14
// speedup vs baseline: 1.7062x; 1.7062x over previous
#include <cuda_runtime.h>
#include <cuda_bf16.h>
#include <mma.h>
#include <math.h>

using namespace nvcuda;

#define B_TOT 16384
#define S_DIM 300
#define A_DIM 30
#define M_PROTO 16
#define NT 256
#define ROWS 16
#define NBLK (B_TOT / ROWS)
#define DH 260
#define LDA 312      // A (state bf16) row stride: 624B, 16B-aligned, 2-way
#define LDB 264      // W1 chunk stride: 528B, 2-way
#define LDH 264      // h stride
#define LDG2 136     // G chunk stride: 272B, 2-way
#define BCH (16 * LDB)   // 4224 elems per W1 buffer
#define GCH (16 * LDG2)  // 2176 elems per G buffer

// fp32 intermediates (precompute1)
__device__ float G_g[256 * 128];
__device__ float c_g[128];
__device__ float conc_g[M_PROTO * A_DIM];
// bf16 hi/lo split tables (precompute2)
__device__ __align__(16) __nv_bfloat16 W1hi_g[304 * 256];
__device__ __align__(16) __nv_bfloat16 W1lo_g[304 * 256];
__device__ __align__(16) __nv_bfloat16 Ghi_g[256 * 128];
__device__ __align__(16) __nv_bfloat16 Glo_g[256 * 128];

// ---------------------------------------------------------------------------
// Precompute1: blocks 0..255 -> G row k; 256 -> c_g; 257..272 -> conc_g[m]
// ---------------------------------------------------------------------------
__global__ void __launch_bounds__(256) precompute_kernel(
    const float* __restrict__ pk, const float* __restrict__ enc_W2,
    const float* __restrict__ enc_b2, const float* __restrict__ dW1,
    const float* __restrict__ db1, const float* __restrict__ dW2,
    const float* __restrict__ db2) {
    const int bk = blockIdx.x;
    const int t = threadIdx.x;
    if (bk < 256) {
        __shared__ float w2row[2048];
        __shared__ float pks[16 * 257];
        __shared__ float part[256];
        for (int i = t; i < 2048; i += 256) w2row[i] = enc_W2[bk * 2048 + i];
        for (int i = t; i < 4096; i += 256)
            pks[(i >> 8) * 257 + (i & 255)] = pk[i];
        __syncthreads();
        const int mn = t & 127, half = t >> 7;
        const int m = mn >> 4, n = mn & 15;
        const float* wr = w2row + m * 256 + half * 128;
        const float* pr = pks + n * 257 + half * 128;
        float s = 0.f;
        #pragma unroll 8
        for (int e = 0; e < 128; e++) s += wr[e] * pr[e];
        part[t] = s;
        __syncthreads();
        if (t < 128) G_g[bk * 128 + t] = (part[t] + part[t + 128]) * 0.0625f;
    } else if (bk == 256) {
        __shared__ float part[256];
        const int mn = t & 127, half = t >> 7;
        const int m = mn >> 4, n = mn & 15;
        const float4* br = (const float4*)(enc_b2 + m * 256 + half * 128);
        const float4* pr = (const float4*)(pk + n * 256 + half * 128);
        float s = 0.f;
        #pragma unroll 8
        for (int e = 0; e < 32; e++) {
            const float4 b4 = __ldg(&br[e]);
            const float4 p4 = __ldg(&pr[e]);
            s += b4.x * p4.x + b4.y * p4.y + b4.z * p4.z + b4.w * p4.w;
        }
        part[t] = s;
        __syncthreads();
        if (t < 128) c_g[t] = (part[t] + part[t + 128]) * 0.0625f;
    } else {
        const int m = bk - 257;
        __shared__ float part[256];
        __shared__ float hd[128];
        const int h = t & 127, eh = t >> 7;
        const float* pkm = pk + m * 256 + eh * 128;
        const float* wcol = dW1 + (m * 256 + eh * 128) * 128 + h;
        float s = 0.f;
        #pragma unroll 8
        for (int e = 0; e < 128; e++) s += pkm[e] * wcol[e * 128];
        part[t] = s;
        __syncthreads();
        if (t < 128)
            hd[t] = fmaxf(part[t] + part[t + 128] + db1[m * 128 + t], 0.f);
        __syncthreads();
        if (t < A_DIM) {
            float s2 = db2[m * A_DIM + t];
            const float* w2 = dW2 + m * 128 * A_DIM + t;
            #pragma unroll 8
            for (int h2 = 0; h2 < 128; h2++)
                s2 += hd[h2] * __ldg(w2 + h2 * A_DIM);
            conc_g[m * A_DIM + t] = fmaxf(s2, 0.f) + log1pf(expf(-fabsf(s2)));
        }
    }
}

// ---------------------------------------------------------------------------
// Precompute2: bf16 hi/lo split of W1 (K padded 300->304) and G
// ---------------------------------------------------------------------------
__global__ void __launch_bounds__(256) convert_kernel(const float* __restrict__ W1) {
    const int idx = blockIdx.x * 256 + threadIdx.x;
    if (idx < 304 * 256) {
        const int k = idx >> 8;
        const float w = (k < 300) ? W1[idx] : 0.f;   // idx = k*256+n
        const __nv_bfloat16 hi = __float2bfloat16(w);
        W1hi_g[idx] = hi;
        W1lo_g[idx] = __float2bfloat16(w - __bfloat162float(hi));
    } else {
        const int j = idx - 304 * 256;
        if (j < 256 * 128) {
            const float g = G_g[j];
            const __nv_bfloat16 hi = __float2bfloat16(g);
            Ghi_g[j] = hi;
            Glo_g[j] = __float2bfloat16(g - __bfloat162float(hi));
        }
    }
}

// ---------------------------------------------------------------------------
// Main kernel: 1024 blocks x 256 threads (8 warps), 16 batch rows/block.
// wmma bf16 hi/lo split (3 mma/tile), padded strides, reg double-buffering.
// ---------------------------------------------------------------------------
__global__ void __launch_bounds__(NT, 2) main_kernel(
    const float* __restrict__ state, const float* __restrict__ fitness,
    const float* __restrict__ pk, const float* __restrict__ b1,
    const float* __restrict__ ln_g, const float* __restrict__ ln_b,
    const float* __restrict__ tc_W, const float* __restrict__ tc_b,
    const float* __restrict__ tc_cW, const float* __restrict__ tc_cb,
    const float* __restrict__ w_prev, float* __restrict__ out) {
    extern __shared__ char smraw[];
    float* st          = (float*)smraw;                    // 4800 f (19200 B)
    float* dh          = (float*)(smraw + 19200);          // 16x260 f (16640 B)
    __nv_bfloat16* Ahi = (__nv_bfloat16*)(smraw + 35840);  // 16x312 (9984 B)
    __nv_bfloat16* Alo = (__nv_bfloat16*)(smraw + 45824);  // 9984 B
    __nv_bfloat16* Bhi = (__nv_bfloat16*)(smraw + 55808);  // 2x4224 (16896 B)
    __nv_bfloat16* Blo = (__nv_bfloat16*)(smraw + 72704);  // 16896 B
    float* dds         = (float*)(smraw + 89600);          // 256 f
    float* concs       = (float*)(smraw + 90624);          // 480 f
    float* stats       = (float*)(smraw + 92544);          // 48 f
    float* lgt         = st;                               // alias (st dead)
    __nv_bfloat16* hhi = Ahi;                              // alias, stride LDH
    __nv_bfloat16* hlo = Alo;

    const int tid = threadIdx.x;
    const int lane = tid & 31;
    const int wid = tid >> 5;
    const int b0 = blockIdx.x * ROWS;
    const unsigned FULL = 0xffffffffu;

    // ---- cooperative loads ----
    {
        const float4* gsrc = (const float4*)(state + (size_t)b0 * S_DIM);
        float4* sdst = (float4*)st;
        for (int i = tid; i < 1200; i += NT) sdst[i] = gsrc[i];
        for (int i = tid; i < M_PROTO * A_DIM; i += NT) concs[i] = conc_g[i];
    }
    __syncthreads();

    // ---- A = st split into bf16 hi/lo, stride LDA, K padded to 304+ ----
    for (int i = tid; i < 16 * LDA; i += NT) {
        const int r = i / LDA, k = i - r * LDA;
        const float v = (k < 300) ? st[r * 300 + k] : 0.f;
        const __nv_bfloat16 hi = __float2bfloat16(v);
        Ahi[i] = hi;
        Alo[i] = __float2bfloat16(v - __bfloat162float(hi));
    }

    // ---- stage 1: market features + danger + crisis (warp: 2 rows) ----
    {
        const int rA = wid, rB = wid + 8;
        const float* sA = st + rA * S_DIM;
        const float* sB = st + rB * S_DIM;
        float mfa[12], mfb[12];
        #pragma unroll
        for (int pass = 0; pass < 2; pass++) {
            const float* srow = pass ? sB : sA;
            float* mf = pass ? mfb : mfa;
            float p = 0.f, sh = 0.f;
            if (lane < 30) { p = srow[1 + lane]; sh = srow[31 + lane]; }
            float sp = p, spp = p * p, sps = p * sh;
            #pragma unroll
            for (int m2 = 16; m2 >= 1; m2 >>= 1) {
                sp  += __shfl_xor_sync(FULL, sp, m2);
                spp += __shfl_xor_sync(FULL, spp, m2);
                sps += __shfl_xor_sync(FULL, sps, m2);
            }
            const float bal = srow[0];
            const float mean = sp * (1.f / 30.f);
            const float var = fmaxf((spp - 30.f * mean * mean) * (1.f / 29.f), 0.f);
            mf[0] = bal; mf[1] = mean;
            mf[2] = sqrtf(var) + 1e-8f;
            mf[3] = bal / (bal + sps + 1e-8f);
            #pragma unroll
            for (int i = 0; i < 8; i++) mf[4 + i] = srow[61 + 30 * i];
        }
        float cpA = 0.f, cpB = 0.f;
        #pragma unroll
        for (int i = 0; i < 8; i++) {
            const int j = lane + 32 * i;
            const float bj = tc_b[j];
            float aA = bj, aB = bj;
            #pragma unroll
            for (int f = 0; f < 12; f++) {
                const float w = tc_W[f * 256 + j];
                aA += mfa[f] * w; aB += mfb[f] * w;
            }
            const float dA = tanhf(aA), dB = tanhf(aB);
            dh[rA * DH + j] = dA;
            dh[rB * DH + j] = dB;
            const float cw = tc_cW[j];
            cpA += dA * cw; cpB += dB * cw;
        }
        #pragma unroll
        for (int m2 = 16; m2 >= 1; m2 >>= 1) {
            cpA += __shfl_xor_sync(FULL, cpA, m2);
            cpB += __shfl_xor_sync(FULL, cpB, m2);
        }
        if (lane == 0) {
            const float cb = tc_cb[0];
            stats[32 + rA] = 1.f / (1.f + expf(-(cpA + cb)));
            stats[32 + rB] = 1.f / (1.f + expf(-(cpB + cb)));
        }
    }
    __syncthreads();

    // ---- dd[r][n] (fp32 exact) + W1 chunk-0 prologue staging ----
    {
        const int n = tid >> 4, kq = tid & 15;
        float pkc[16];
        {
            const float4* pr = (const float4*)(pk + n * 256 + kq * 16);
            #pragma unroll
            for (int i = 0; i < 4; i++) {
                const float4 p4 = __ldg(&pr[i]);
                pkc[i * 4 + 0] = p4.x; pkc[i * 4 + 1] = p4.y;
                pkc[i * 4 + 2] = p4.z; pkc[i * 4 + 3] = p4.w;
            }
        }
        #pragma unroll 4
        for (int r = 0; r < ROWS; r++) {
            const float* dr = dh + r * DH + kq * 16;
            float s = 0.f;
            #pragma unroll
            for (int i = 0; i < 4; i++) {
                const float4 d4 = *(const float4*)&dr[i * 4];
                s += d4.x * pkc[i * 4] + d4.y * pkc[i * 4 + 1] +
                     d4.z * pkc[i * 4 + 2] + d4.w * pkc[i * 4 + 3];
            }
            #pragma unroll
            for (int m2 = 8; m2 >= 1; m2 >>= 1) s += __shfl_xor_sync(FULL, s, m2);
            if (kq == 0) dds[r * 16 + n] = s * 0.0625f;
        }
        // prologue: stage W1 chunk 0 into buffer 0 (padded stride)
        const uint4 h0 = ((const uint4*)W1hi_g)[tid];
        const uint4 h1 = ((const uint4*)W1hi_g)[tid + 256];
        const uint4 l0 = ((const uint4*)W1lo_g)[tid];
        const uint4 l1 = ((const uint4*)W1lo_g)[tid + 256];
        const int r8 = tid >> 5, c8 = tid & 31;   // 32 uint4 per 256-col row
        uint4* bh4 = (uint4*)Bhi;
        uint4* bl4 = (uint4*)Blo;
        bh4[r8 * 33 + c8] = h0; bh4[(r8 + 8) * 33 + c8] = h1;
        bl4[r8 * 33 + c8] = l0; bl4[(r8 + 8) * 33 + c8] = l1;
    }
    __syncthreads();

    // ---- W1 GEMM: 19 k-chunks, reg double-buffer, padded fragments ----
    {
        const int n0 = wid * 32;
        const int r8 = tid >> 5, c8 = tid & 31;
        wmma::fragment<wmma::matrix_a, 16, 16, 16, __nv_bfloat16, wmma::row_major> fah, fal;
        wmma::fragment<wmma::matrix_b, 16, 16, 16, __nv_bfloat16, wmma::row_major> fbh0, fbl0, fbh1, fbl1;
        wmma::fragment<wmma::accumulator, 16, 16, 16, float> c0, c1;
        wmma::fill_fragment(c0, 0.f);
        wmma::fill_fragment(c1, 0.f);
        uint4 ph0, ph1, pl0, pl1;
        for (int kc = 0; kc < 19; kc++) {
            const int s = kc & 1;
            if (kc < 18) {   // prefetch next chunk into regs (overlaps mma)
                const int base = (kc + 1) * 512;
                ph0 = ((const uint4*)W1hi_g)[base + tid];
                ph1 = ((const uint4*)W1hi_g)[base + 256 + tid];
                pl0 = ((const uint4*)W1lo_g)[base + tid];
                pl1 = ((const uint4*)W1lo_g)[base + 256 + tid];
            }
            const __nv_bfloat16* bsh = Bhi + s * BCH;
            const __nv_bfloat16* bsl = Blo + s * BCH;
            wmma::load_matrix_sync(fah, Ahi + kc * 16, LDA);
            wmma::load_matrix_sync(fal, Alo + kc * 16, LDA);
            wmma::load_matrix_sync(fbh0, bsh + n0, LDB);
            wmma::load_matrix_sync(fbl0, bsl + n0, LDB);
            wmma::load_matrix_sync(fbh1, bsh + n0 + 16, LDB);
            wmma::load_matrix_sync(fbl1, bsl + n0 + 16, LDB);
            wmma::mma_sync(c0, fah, fbh0, c0);
            wmma::mma_sync(c0, fah, fbl0, c0);
            wmma::mma_sync(c0, fal, fbh0, c0);
            wmma::mma_sync(c1, fah, fbh1, c1);
            wmma::mma_sync(c1, fah, fbl1, c1);
            wmma::mma_sync(c1, fal, fbh1, c1);
            __syncthreads();
            if (kc < 18) {
                uint4* bh4 = (uint4*)(Bhi + (s ^ 1) * BCH);
                uint4* bl4 = (uint4*)(Blo + (s ^ 1) * BCH);
                bh4[r8 * 33 + c8] = ph0; bh4[(r8 + 8) * 33 + c8] = ph1;
                bl4[r8 * 33 + c8] = pl0; bl4[(r8 + 8) * 33 + c8] = pl1;
            }
            __syncthreads();
        }
        wmma::store_matrix_sync(dh + n0, c0, DH, wmma::mem_row_major);
        wmma::store_matrix_sync(dh + n0 + 16, c1, DH, wmma::mem_row_major);
    }
    __syncthreads();

    // ---- layernorm stats (b1 folded at read) ----
    for (int rr = 0; rr < 2; rr++) {
        const int r = wid + rr * 8;
        float s1 = 0.f, s2 = 0.f;
        #pragma unroll
        for (int i = 0; i < 8; i++) {
            const int j = lane + 32 * i;
            const float v = dh[r * DH + j] + b1[j];
            s1 += v; s2 += v * v;
        }
        #pragma unroll
        for (int m2 = 16; m2 >= 1; m2 >>= 1) {
            s1 += __shfl_xor_sync(FULL, s1, m2);
            s2 += __shfl_xor_sync(FULL, s2, m2);
        }
        if (lane == 0) {
            const float mu = s1 * (1.f / 256.f);
            const float var = s2 * (1.f / 256.f) - mu * mu;
            stats[r] = mu;
            stats[16 + r] = rsqrtf(fmaxf(var, 0.f) + 1e-5f);
        }
    }
    __syncthreads();
    // ---- normalize + relu -> bf16 hi/lo h (stride LDH); stage G chunk 0 ----
    {
        const float g = ln_g[tid], bb = ln_b[tid], bias = b1[tid];
        #pragma unroll
        for (int r = 0; r < ROWS; r++) {
            const float raw = dh[r * DH + tid] + bias;
            const float v = fmaxf((raw - stats[r]) * stats[16 + r] * g + bb, 0.f);
            const __nv_bfloat16 hi = __float2bfloat16(v);
            hhi[r * LDH + tid] = hi;
            hlo[r * LDH + tid] = __float2bfloat16(v - __bfloat162float(hi));
        }
        const int r4 = tid >> 4, c4 = tid & 15;   // 16 uint4 per 128-col row
        ((uint4*)Bhi)[r4 * 17 + c4] = ((const uint4*)Ghi_g)[tid];
        ((uint4*)Blo)[r4 * 17 + c4] = ((const uint4*)Glo_g)[tid];
    }
    __syncthreads();

    // ---- logits GEMM: 16 k-chunks of G, same pipelining ----
    {
        const int n0 = wid * 16;
        const int r4 = tid >> 4, c4 = tid & 15;
        wmma::fragment<wmma::matrix_a, 16, 16, 16, __nv_bfloat16, wmma::row_major> fah, fal;
        wmma::fragment<wmma::matrix_b, 16, 16, 16, __nv_bfloat16, wmma::row_major> fbh, fbl;
        wmma::fragment<wmma::accumulator, 16, 16, 16, float> cl;
        wmma::fill_fragment(cl, 0.f);
        uint4 qh, ql;
        for (int kc = 0; kc < 16; kc++) {
            const int s = kc & 1;
            if (kc < 15) {
                qh = ((const uint4*)Ghi_g)[(kc + 1) * 256 + tid];
                ql = ((const uint4*)Glo_g)[(kc + 1) * 256 + tid];
            }
            wmma::load_matrix_sync(fah, hhi + kc * 16, LDH);
            wmma::load_matrix_sync(fal, hlo + kc * 16, LDH);
            wmma::load_matrix_sync(fbh, Bhi + s * GCH + n0, LDG2);
            wmma::load_matrix_sync(fbl, Blo + s * GCH + n0, LDG2);
            wmma::mma_sync(cl, fah, fbh, cl);
            wmma::mma_sync(cl, fah, fbl, cl);
            wmma::mma_sync(cl, fal, fbh, cl);
            __syncthreads();
            if (kc < 15) {
                ((uint4*)(Bhi + (s ^ 1) * GCH))[r4 * 17 + c4] = qh;
                ((uint4*)(Blo + (s ^ 1) * GCH))[r4 * 17 + c4] = ql;
            }
            __syncthreads();
        }
        wmma::store_matrix_sync(lgt + n0, cl, 128, wmma::mem_row_major);
    }
    __syncthreads();

    // ---- softmax over protos, weight mixing, action softmax (warp/row) ----
    for (int rr = 0; rr < 2; rr++) {
        const int r = wid + rr * 8;
        const int n = lane & 15;
        const int mh = lane >> 4;
        float wot = 0.f;
        #pragma unroll
        for (int mm = 0; mm < 4; mm++) {
            const int m = mm * 2 + mh;
            const float v = lgt[r * 128 + m * 16 + n] + c_g[m * 16 + n] + dds[r * 16 + n];
            float mx = v;
            #pragma unroll
            for (int m2 = 8; m2 >= 1; m2 >>= 1) mx = fmaxf(mx, __shfl_xor_sync(FULL, mx, m2));
            const float e = expf(v - mx);
            float s = e;
            #pragma unroll
            for (int m2 = 8; m2 >= 1; m2 >>= 1) s += __shfl_xor_sync(FULL, s, m2);
            wot += e / s;
        }
        wot += __shfl_xor_sync(FULL, wot, 16);
        wot *= 0.125f;

        const float f = fitness[(b0 + r) * 16 + n];
        float wr = w_prev[n] * expf(0.1f * f);
        float swr = wr;
        #pragma unroll
        for (int m2 = 8; m2 >= 1; m2 >>= 1) swr += __shfl_xor_sync(FULL, swr, m2);
        wr /= (swr + 1e-8f);

        const float crisis = stats[32 + r];
        const float alpha = 0.06f + 0.24f * (1.f - crisis);
        float w = alpha * wot + (1.f - alpha) * wr;
        float sw = w;
        #pragma unroll
        for (int m2 = 8; m2 >= 1; m2 >>= 1) sw += __shfl_xor_sync(FULL, sw, m2);
        w /= (sw + 1e-8f);
        if (lane < 16) dds[r * 16 + n] = w;
        __syncwarp();

        float mix = __int_as_float(0xff800000);
        if (lane < 30) {
            mix = 1.f;
            #pragma unroll
            for (int m = 0; m < 16; m++) mix += dds[r * 16 + m] * concs[m * 30 + lane];
        }
        float mx = mix;
        #pragma unroll
        for (int m2 = 16; m2 >= 1; m2 >>= 1) mx = fmaxf(mx, __shfl_xor_sync(FULL, mx, m2));
        float e = (lane < 30) ? expf(mix - mx) : 0.f;
        float s = e;
        #pragma unroll
        for (int m2 = 16; m2 >= 1; m2 >>= 1) s += __shfl_xor_sync(FULL, s, m2);
        float p = e / s;
        float sp = p;
        #pragma unroll
        for (int m2 = 16; m2 >= 1; m2 >>= 1) sp += __shfl_xor_sync(FULL, sp, m2);
        p = p / (sp + 1e-8f);
        if (lane < 30) out[(b0 + r) * 30 + lane] = p;
    }
}

// ---------------------------------------------------------------------------
extern "C" void kernel_launch(void* const* d_in, const int* in_sizes, int n_in,
                              void* d_out, int out_size) {
    const float* state   = (const float*)d_in[0];
    const float* fitness = (const float*)d_in[1];
    const float* pk      = (const float*)d_in[2];
    const float* W1      = (const float*)d_in[3];
    const float* b1      = (const float*)d_in[4];
    const float* ln_g    = (const float*)d_in[5];
    const float* ln_b    = (const float*)d_in[6];
    const float* W2      = (const float*)d_in[7];
    const float* b2      = (const float*)d_in[8];
    const float* dW1     = (const float*)d_in[9];
    const float* db1     = (const float*)d_in[10];
    const float* dW2     = (const float*)d_in[11];
    const float* db2     = (const float*)d_in[12];
    const float* tcW     = (const float*)d_in[13];
    const float* tcb     = (const float*)d_in[14];
    const float* tccW    = (const float*)d_in[15];
    const float* tccb    = (const float*)d_in[16];
    const float* w_prev  = (const float*)d_in[19];
    float* out = (float*)d_out;

    precompute_kernel<<<273, 256>>>(pk, W2, b2, dW1, db1, dW2, db2);
    convert_kernel<<<432, 256>>>(W1);

    const int smem_bytes = 92736;
    cudaFuncSetAttribute(main_kernel, cudaFuncAttributeMaxDynamicSharedMemorySize,
                         smem_bytes);
    main_kernel<<<NBLK, NT, smem_bytes>>>(state, fitness, pk, b1, ln_g, ln_b,
                                          tcW, tcb, tccW, tccb, w_prev, out);
}